// round 11
// baseline (speedup 1.0000x reference)
#include <cuda_runtime.h>
#include <cuda_bf16.h>
#include <cstdint>

#define SS 512
#define BB 256
#define II 64
#define HH 512
#define G4 2048
#define NCTA 128

// ---------------- static device scratch (no allocs allowed) ----------------
__device__ float          g_xw[(size_t)SS * BB * G4];      // layer-1 input projection (fp32)
__device__ __nv_bfloat16  g_h1_hi[(size_t)SS * BB * HH], g_h1_lo[(size_t)SS * BB * HH];
__device__ __nv_bfloat16  g_h2_hi[(size_t)SS * BB * HH], g_h2_lo[(size_t)SS * BB * HH];
__device__ __nv_bfloat16  g_h3_hi[(size_t)SS * BB * HH], g_h3_lo[(size_t)SS * BB * HH];
__device__ __nv_bfloat16  g_x_hi[(size_t)SS * BB * II],  g_x_lo[(size_t)SS * BB * II];

__device__ __nv_bfloat16 g_wih1_hi[G4 * II], g_wih1_lo[G4 * II];
__device__ __nv_bfloat16 g_whh1_hi[G4 * HH], g_whh1_lo[G4 * HH];
__device__ __nv_bfloat16 g_wih2_hi[G4 * HH], g_wih2_lo[G4 * HH];
__device__ __nv_bfloat16 g_whh2_hi[G4 * HH], g_whh2_lo[G4 * HH];
__device__ __nv_bfloat16 g_wih3_hi[G4 * HH], g_wih3_lo[G4 * HH];
__device__ __nv_bfloat16 g_whh3_hi[G4 * HH], g_whh3_lo[G4 * HH];

// per-batch-group barriers: 4 groups, each counter/gen on its own 128B line
__device__ unsigned g_bcnt[4 * 32];
__device__ unsigned g_bgen[4 * 32];

// k-permutation within each 16-block: stored position q holds logical l16(q)
__device__ __forceinline__ int l16(int q) {
    return ((q >> 2) << 1) | (q & 1) | ((q & 2) << 2);
}

// ---------------- helpers ----------------
__device__ __forceinline__ void split_bf16(float v, __nv_bfloat16& hi, __nv_bfloat16& lo) {
    hi = __float2bfloat16(v);
    lo = __float2bfloat16(v - __bfloat162float(hi));
}

__device__ __forceinline__ void mma16816(float* d, const unsigned* a, const unsigned* b) {
    asm volatile(
        "mma.sync.aligned.m16n8k16.row.col.f32.bf16.bf16.f32 "
        "{%0,%1,%2,%3}, {%4,%5,%6,%7}, {%8,%9}, {%0,%1,%2,%3};\n"
        : "+f"(d[0]), "+f"(d[1]), "+f"(d[2]), "+f"(d[3])
        : "r"(a[0]), "r"(a[1]), "r"(a[2]), "r"(a[3]), "r"(b[0]), "r"(b[1]));
}

__device__ __forceinline__ unsigned smem_u32(const void* p) {
    unsigned a;
    asm("{ .reg .u64 t; cvta.to.shared.u64 t, %1; cvt.u32.u64 %0, t; }" : "=r"(a) : "l"(p));
    return a;
}

__device__ __forceinline__ void cp16(unsigned dst, const void* src) {
    asm volatile("cp.async.cg.shared.global [%0], [%1], 16;" :: "r"(dst), "l"(src));
}
__device__ __forceinline__ void cp_commit() {
    asm volatile("cp.async.commit_group;");
}
template <int N>
__device__ __forceinline__ void cp_wait() {
    asm volatile("cp.async.wait_group %0;" :: "n"(N));
}

__device__ __forceinline__ float fsigmoid(float x) {
    return 1.f / (1.f + __expf(-x));
}
__device__ __forceinline__ float felu(float x) {
    return x > 0.f ? x : (__expf(x) - 1.f);
}

// group barrier: 32 CTAs of one batch group
__device__ __forceinline__ void gbar_g(unsigned target, int grp) {
    __syncthreads();
    if (threadIdx.x == 0) {
        unsigned* cnt = &g_bcnt[grp * 32];
        unsigned* gen = &g_bgen[grp * 32];
        __threadfence();
        if (atomicAdd(cnt, 1u) == 31u) {
            *cnt = 0;
            __threadfence();
            atomicExch(gen, target);
        } else {
            unsigned g;
            do {
                asm volatile("ld.global.acquire.gpu.u32 %0, [%1];" : "=r"(g) : "l"(gen));
            } while (g < target);
        }
    }
    __syncthreads();
}

__global__ void k_bar_init() {
    int i = threadIdx.x;
    if (i < 4 * 32) { g_bcnt[i] = 0; g_bgen[i] = 0; }
}

// ---------------- fused split kernel (weights + x), k-permuted ----------------
#define NW1 (G4 * II)
#define NWH (G4 * HH)
#define NX  ((size_t)SS * BB * II)
#define NSPLIT (NW1 + 5 * NWH + NX)

__global__ void k_split_all(const float* __restrict__ x,
                            const float* __restrict__ wih1, const float* __restrict__ whh1,
                            const float* __restrict__ wih2, const float* __restrict__ whh2,
                            const float* __restrict__ wih3, const float* __restrict__ whh3) {
    size_t i = (size_t)blockIdx.x * 256 + threadIdx.x;
    if (i >= NSPLIT) return;
    if (i < NW1) {
        int j = (int)i;
        int p = j % II, row = j / II;
        int l = (p & ~15) | l16(p & 15);
        split_bf16(wih1[row * II + l], g_wih1_hi[j], g_wih1_lo[j]);
    } else if (i < NW1 + 5 * (size_t)NWH) {
        size_t r = i - NW1;
        int t = (int)(r >> 20);              // NWH = 2^20
        int j = (int)(r & (NWH - 1));
        int p = j % HH, row = j / HH;
        int l = (p & ~15) | l16(p & 15);
        const float* src;
        __nv_bfloat16 *hi, *lo;
        switch (t) {
            case 0: src = whh1; hi = g_whh1_hi; lo = g_whh1_lo; break;
            case 1: src = wih2; hi = g_wih2_hi; lo = g_wih2_lo; break;
            case 2: src = whh2; hi = g_whh2_hi; lo = g_whh2_lo; break;
            case 3: src = wih3; hi = g_wih3_hi; lo = g_wih3_lo; break;
            default: src = whh3; hi = g_whh3_hi; lo = g_whh3_lo; break;
        }
        split_bf16(src[(size_t)row * HH + l], hi[j], lo[j]);
    } else {
        size_t j = i - (NW1 + 5 * (size_t)NWH);
        int p = (int)(j % II);
        int b = (int)((j / II) % BB);
        int s = (int)(j / ((size_t)II * BB));
        int l = (p & ~15) | l16(p & 15);
        split_bf16(x[((size_t)b * SS + s) * II + l], g_x_hi[j], g_x_lo[j]);
    }
}

// ---------------- xw GEMM for layer 1 only (K=64; round-5 proven body) --------
#define XBM 128
#define XBN 128
#define XBK 32
#define XST 4
#define XAP 40
#define XW_SMEM (XST * (XBM + XBN) * XAP * 2 * 2)   // 163840 bytes

__global__ __launch_bounds__(256) void k_gemm_xw(const float* __restrict__ bias) {
    const __nv_bfloat16 *Ah = g_x_hi, *Al = g_x_lo, *Wh = g_wih1_hi, *Wl = g_wih1_lo;
    const int K = II;

    extern __shared__ char xsm[];
    __nv_bfloat16* sAh = (__nv_bfloat16*)xsm;
    __nv_bfloat16* sAl = sAh + XST * XBM * XAP;
    __nv_bfloat16* sWh = sAl + XST * XBM * XAP;
    __nv_bfloat16* sWl = sWh + XST * XBN * XAP;

    unsigned uAh = smem_u32(sAh), uAl = smem_u32(sAl);
    unsigned uWh = smem_u32(sWh), uWl = smem_u32(sWl);

    int tid = threadIdx.x;
    int m0 = blockIdx.y * XBM;
    int n0 = blockIdx.x * XBN;
    int warp = tid >> 5, lane = tid & 31;
    int wm = warp >> 1, wn = warp & 1;
    int gq = lane >> 2, tg = lane & 3;

    int lrow = tid >> 1;
    int lcol = (tid & 1) * 16;

    float acc[2][8][4];
#pragma unroll
    for (int mi = 0; mi < 2; mi++)
#pragma unroll
        for (int ni = 0; ni < 8; ni++)
#pragma unroll
            for (int r = 0; r < 4; r++) acc[mi][ni][r] = 0.f;

    int nkt = K / XBK;   // 2

    auto issue = [&](int kt, int st) {
        size_t ga = (size_t)(m0 + lrow) * K + kt * XBK + lcol;
        size_t gw = (size_t)(n0 + lrow) * K + kt * XBK + lcol;
        unsigned da = (unsigned)(((st * XBM + lrow) * XAP + lcol) * 2);
        unsigned dw = (unsigned)(((st * XBN + lrow) * XAP + lcol) * 2);
        cp16(uAh + da, Ah + ga);       cp16(uAh + da + 16, Ah + ga + 8);
        cp16(uAl + da, Al + ga);       cp16(uAl + da + 16, Al + ga + 8);
        cp16(uWh + dw, Wh + gw);       cp16(uWh + dw + 16, Wh + gw + 8);
        cp16(uWl + dw, Wl + gw);       cp16(uWl + dw + 16, Wl + gw + 8);
        cp_commit();
    };

    int npro = nkt < (XST - 1) ? nkt : (XST - 1);
    for (int p = 0; p < npro; p++) issue(p, p);

    for (int kt = 0; kt < nkt; kt++) {
        int rem = nkt - kt - 1;
        if (rem >= 2) cp_wait<2>();
        else if (rem == 1) cp_wait<1>();
        else cp_wait<0>();
        __syncthreads();

        if (kt + XST - 1 < nkt) issue(kt + XST - 1, (kt + XST - 1) % XST);

        int st = kt % XST;
        const __nv_bfloat16* cAh = sAh + st * XBM * XAP;
        const __nv_bfloat16* cAl = sAl + st * XBM * XAP;
        const __nv_bfloat16* cWh = sWh + st * XBN * XAP;
        const __nv_bfloat16* cWl = sWl + st * XBN * XAP;

#pragma unroll
        for (int kc = 0; kc < XBK; kc += 16) {
            unsigned ah[2][4], al[2][4], bh[8][2], bl[8][2];
#pragma unroll
            for (int mi = 0; mi < 2; mi++) {
                int r = wm * 32 + mi * 16 + gq;
                ah[mi][0] = *(unsigned*)&cAh[r * XAP + kc + 2 * tg];
                ah[mi][1] = *(unsigned*)&cAh[(r + 8) * XAP + kc + 2 * tg];
                ah[mi][2] = *(unsigned*)&cAh[r * XAP + kc + 2 * tg + 8];
                ah[mi][3] = *(unsigned*)&cAh[(r + 8) * XAP + kc + 2 * tg + 8];
                al[mi][0] = *(unsigned*)&cAl[r * XAP + kc + 2 * tg];
                al[mi][1] = *(unsigned*)&cAl[(r + 8) * XAP + kc + 2 * tg];
                al[mi][2] = *(unsigned*)&cAl[r * XAP + kc + 2 * tg + 8];
                al[mi][3] = *(unsigned*)&cAl[(r + 8) * XAP + kc + 2 * tg + 8];
            }
#pragma unroll
            for (int ni = 0; ni < 8; ni++) {
                int n = wn * 64 + ni * 8 + gq;
                bh[ni][0] = *(unsigned*)&cWh[n * XAP + kc + 2 * tg];
                bh[ni][1] = *(unsigned*)&cWh[n * XAP + kc + 2 * tg + 8];
                bl[ni][0] = *(unsigned*)&cWl[n * XAP + kc + 2 * tg];
                bl[ni][1] = *(unsigned*)&cWl[n * XAP + kc + 2 * tg + 8];
            }
#pragma unroll
            for (int mi = 0; mi < 2; mi++)
#pragma unroll
                for (int ni = 0; ni < 8; ni++) {
                    mma16816(acc[mi][ni], ah[mi], bh[ni]);
                    mma16816(acc[mi][ni], ah[mi], bl[ni]);
                    mma16816(acc[mi][ni], al[mi], bh[ni]);
                }
        }
    }

#pragma unroll
    for (int mi = 0; mi < 2; mi++)
#pragma unroll
        for (int ni = 0; ni < 8; ni++) {
            int row = m0 + wm * 32 + mi * 16 + gq;
            int col = n0 + wn * 64 + ni * 8 + 2 * tg;
            float b0v = bias[col], b1v = bias[col + 1];
            g_xw[(size_t)row * G4 + col]           = acc[mi][ni][0] + b0v;
            g_xw[(size_t)row * G4 + col + 1]       = acc[mi][ni][1] + b1v;
            g_xw[(size_t)(row + 8) * G4 + col]     = acc[mi][ni][2] + b0v;
            g_xw[(size_t)(row + 8) * G4 + col + 1] = acc[mi][ni][3] + b1v;
        }
}

// ---------------- 3-layer wavefront persistent kernel ----------------
// 128 CTAs x 256 threads; CTA = (batch group of 64) x (16 hid units x 4 gates).
// Wall step t: layer1 step t, layer2 step t-1, layer3 step t-2. ONE group barrier/step.
// Whh1 resident in SMEM; W2/W3 (Wih+Whh) streamed per k-tile; h streamed.
// SMEM (bytes):
//   0      sW1h[64][528]     67584
//   67584  sW1l[64][528]     67584
//   135168 A-stage hi 2x(64x80x2B) = 20480
//   155648 A-stage lo 20480
//   176128 W-stage hi 20480
//   196608 W-stage lo 20480
// total 217088
#define WAV_SMEM 217088
#define SWP 528
#define STP 80
#define TILB 10240   // bytes per staged buffer (64*80*2)
#define OAHI 135168
#define OALO 155648
#define OWHI 176128
#define OWLO 196608

__global__ __launch_bounds__(256, 1) void k_wave(const float* __restrict__ b2,
                                                 const float* __restrict__ b3) {
    extern __shared__ char sm[];
    __nv_bfloat16 (*sW1h)[SWP] = (__nv_bfloat16(*)[SWP])(sm);
    __nv_bfloat16 (*sW1l)[SWP] = (__nv_bfloat16(*)[SWP])(sm + 67584);

    int tid = threadIdx.x;
    int warp = tid >> 5, lane = tid & 31;
    int bx = blockIdx.x;
    int bhid = bx >> 2;          // 0..31
    int bbat = bx & 3;           // 0..3 (barrier group)
    int m0 = bbat * 64;
    int n0 = bhid * 16;
    int wm = warp >> 1, wn = warp & 1;
    int gq = lane >> 2, tg = lane & 3;

    int row0 = wm * 16 + gq;          // local batch rows row0, row0+8
    int jloc = wn * 8 + 2 * tg;       // logical hidden col within unit block
    int jst  = 4 * tg + 2 * wn;       // stored (permuted) hidden col
    int lrow = tid >> 2;              // loader: 64 rows, 4 threads/row
    int lcol = (tid & 3) * 16;        // chunks at lcol, lcol+8

    // resident Whh1 slice: local row r = g*16+j -> global row g*512 + n0 + j
    for (int idx = tid; idx < 64 * 256; idx += 256) {
        int r = idx >> 8;
        int c = (idx & 255) * 2;
        int grow = (r >> 4) * HH + n0 + (r & 15);
        size_t gi = (size_t)grow * HH + c;
        *(unsigned*)&sW1h[r][c] = *(const unsigned*)&g_whh1_hi[gi];
        *(unsigned*)&sW1l[r][c] = *(const unsigned*)&g_whh1_lo[gi];
    }
    __syncthreads();

    unsigned base = smem_u32(sm);
    unsigned uAhi = base + OAHI, uAlo = base + OALO;
    unsigned uWhi = base + OWHI, uWlo = base + OWLO;

    // biases for layers 2,3 (this thread's 4 gates x 2 cols)
    float b2r[4][2], b3r[4][2];
#pragma unroll
    for (int g = 0; g < 4; g++)
#pragma unroll
        for (int cc = 0; cc < 2; cc++) {
            b2r[g][cc] = b2[g * HH + n0 + jloc + cc];
            b3r[g][cc] = b3[g * HH + n0 + jloc + cc];
        }

    // register-resident cell states (4 cells each: [rr*2+cc])
    float c1s[4] = {0.f, 0.f, 0.f, 0.f};
    float c2s[4] = {0.f, 0.f, 0.f, 0.f};
    float c3s[4] = {0.f, 0.f, 0.f, 0.f};

    // ---- staged-tile issue helpers ----
    auto issueA = [&](const __nv_bfloat16* Ah, const __nv_bfloat16* Al, int kt, int b) {
        const __nv_bfloat16* gh = Ah + (size_t)lrow * HH + kt * 64 + lcol;
        const __nv_bfloat16* gl = Al + (size_t)lrow * HH + kt * 64 + lcol;
        unsigned d = (unsigned)(b * TILB + (lrow * STP + lcol) * 2);
        cp16(uAhi + d, gh);  cp16(uAhi + d + 16, gh + 8);
        cp16(uAlo + d, gl);  cp16(uAlo + d + 16, gl + 8);
    };
    auto issueW = [&](const __nv_bfloat16* Wh, const __nv_bfloat16* Wl, int kt, int b) {
        int grow = (lrow >> 4) * HH + n0 + (lrow & 15);
        const __nv_bfloat16* gh = Wh + (size_t)grow * HH + kt * 64 + lcol;
        const __nv_bfloat16* gl = Wl + (size_t)grow * HH + kt * 64 + lcol;
        unsigned d = (unsigned)(b * TILB + (lrow * STP + lcol) * 2);
        cp16(uWhi + d, gh);  cp16(uWhi + d + 16, gh + 8);
        cp16(uWlo + d, gl);  cp16(uWlo + d + 16, gl + 8);
    };

    // ---- MMA on one staged tile; B from resident Whh1 (kt = global k-tile idx) ----
    auto tile_res = [&](int b, int kt, float* acc) {
        const __nv_bfloat16* cAh = (const __nv_bfloat16*)(sm + OAHI + b * TILB);
        const __nv_bfloat16* cAl = (const __nv_bfloat16*)(sm + OALO + b * TILB);
#pragma unroll
        for (int kc = 0; kc < 64; kc += 16) {
            int kw = kt * 64 + kc;
            unsigned ah[4], al[4], bh[4][2], bl[4][2];
            uint2 t;
            t = *(uint2*)&cAh[row0 * STP + kc + 4 * tg];        ah[0] = t.x; ah[2] = t.y;
            t = *(uint2*)&cAh[(row0 + 8) * STP + kc + 4 * tg];  ah[1] = t.x; ah[3] = t.y;
            t = *(uint2*)&cAl[row0 * STP + kc + 4 * tg];        al[0] = t.x; al[2] = t.y;
            t = *(uint2*)&cAl[(row0 + 8) * STP + kc + 4 * tg];  al[1] = t.x; al[3] = t.y;
#pragma unroll
            for (int g = 0; g < 4; g++) {
                int n = g * 16 + wn * 8 + gq;
                t = *(uint2*)&sW1h[n][kw + 4 * tg];  bh[g][0] = t.x; bh[g][1] = t.y;
                t = *(uint2*)&sW1l[n][kw + 4 * tg];  bl[g][0] = t.x; bl[g][1] = t.y;
            }
#pragma unroll
            for (int g = 0; g < 4; g++) {
                mma16816(acc + g * 4, ah, bh[g]);
                mma16816(acc + g * 4, ah, bl[g]);
                mma16816(acc + g * 4, al, bh[g]);
            }
        }
    };

    // ---- MMA on one staged tile; B from staged W tile ----
    auto tile_str = [&](int b, float* acc) {
        const __nv_bfloat16* cAh = (const __nv_bfloat16*)(sm + OAHI + b * TILB);
        const __nv_bfloat16* cAl = (const __nv_bfloat16*)(sm + OALO + b * TILB);
        const __nv_bfloat16* cWh = (const __nv_bfloat16*)(sm + OWHI + b * TILB);
        const __nv_bfloat16* cWl = (const __nv_bfloat16*)(sm + OWLO + b * TILB);
#pragma unroll
        for (int kc = 0; kc < 64; kc += 16) {
            unsigned ah[4], al[4], bh[4][2], bl[4][2];
            uint2 t;
            t = *(uint2*)&cAh[row0 * STP + kc + 4 * tg];        ah[0] = t.x; ah[2] = t.y;
            t = *(uint2*)&cAh[(row0 + 8) * STP + kc + 4 * tg];  ah[1] = t.x; ah[3] = t.y;
            t = *(uint2*)&cAl[row0 * STP + kc + 4 * tg];        al[0] = t.x; al[2] = t.y;
            t = *(uint2*)&cAl[(row0 + 8) * STP + kc + 4 * tg];  al[1] = t.x; al[3] = t.y;
#pragma unroll
            for (int g = 0; g < 4; g++) {
                int n = g * 16 + wn * 8 + gq;
                t = *(uint2*)&cWh[n * STP + kc + 4 * tg];  bh[g][0] = t.x; bh[g][1] = t.y;
                t = *(uint2*)&cWl[n * STP + kc + 4 * tg];  bl[g][0] = t.x; bl[g][1] = t.y;
            }
#pragma unroll
            for (int g = 0; g < 4; g++) {
                mma16816(acc + g * 4, ah, bh[g]);
                mma16816(acc + g * 4, ah, bl[g]);
                mma16816(acc + g * 4, al, bh[g]);
            }
        }
    };

    // ---- 8-tile part with resident weights (layer 1) ----
    auto part_res = [&](const __nv_bfloat16* Ah, const __nv_bfloat16* Al, float* acc) {
        issueA(Ah, Al, 0, 0); cp_commit();
        for (int kt = 0; kt < 8; kt++) {
            cp_wait<0>();
            __syncthreads();
            if (kt + 1 < 8) { issueA(Ah, Al, kt + 1, (kt + 1) & 1); cp_commit(); }
            tile_res(kt & 1, kt, acc);
        }
    };

    // ---- 8-tile part with streamed weights (layers 2,3) ----
    auto part_str = [&](const __nv_bfloat16* Ah, const __nv_bfloat16* Al,
                        const __nv_bfloat16* Wh, const __nv_bfloat16* Wl, float* acc) {
        issueA(Ah, Al, 0, 0); issueW(Wh, Wl, 0, 0); cp_commit();
        for (int kt = 0; kt < 8; kt++) {
            cp_wait<0>();
            __syncthreads();
            if (kt + 1 < 8) {
                issueA(Ah, Al, kt + 1, (kt + 1) & 1);
                issueW(Wh, Wl, kt + 1, (kt + 1) & 1);
                cp_commit();
            }
            tile_str(kt & 1, acc);
        }
    };

    // ---- epilogue: acc + pre -> activations -> c,h ----
    auto epi = [&](const float* acc, const float* pre, float* cst,
                   __nv_bfloat16* Hh, __nv_bfloat16* Hl, int s) {
#pragma unroll
        for (int rr = 0; rr < 2; rr++) {
            __nv_bfloat16 hh[2], hl[2];
#pragma unroll
            for (int cc = 0; cc < 2; cc++) {
                int fi = rr * 2 + cc;
                float pi = acc[0 * 4 + fi] + pre[0 * 4 + fi];
                float pf = acc[1 * 4 + fi] + pre[1 * 4 + fi];
                float pg = acc[2 * 4 + fi] + pre[2 * 4 + fi];
                float po = acc[3 * 4 + fi] + pre[3 * 4 + fi];
                float iv = fsigmoid(pi);
                float fv = fsigmoid(pf);
                float gv = felu(pg);
                float ov = fsigmoid(po);
                float cn = fv * cst[fi] + iv * gv;
                float hv = ov * felu(cn);
                cst[fi] = cn;
                split_bf16(hv, hh[cc], hl[cc]);
            }
            size_t hidx = ((size_t)s * BB + m0 + row0 + rr * 8) * HH + n0 + jst;
            *(unsigned*)(Hh + hidx) = *(unsigned*)hh;
            *(unsigned*)(Hl + hidx) = *(unsigned*)hl;
        }
    };

    // ================= wavefront loop =================
    for (int t = 0; t < SS + 2; t++) {
        int s1 = t, s2 = t - 1, s3 = t - 2;

        if (s1 < SS) {
            // pre = xw1[s1] (includes bias)
            float pre[16];
            const float* xwb = g_xw + ((size_t)s1 * BB + m0 + row0) * G4;
#pragma unroll
            for (int g = 0; g < 4; g++)
#pragma unroll
                for (int rr = 0; rr < 2; rr++) {
                    float2 v = *(const float2*)(xwb + (size_t)rr * 8 * G4 + g * HH + n0 + jloc);
                    pre[g * 4 + rr * 2 + 0] = v.x;
                    pre[g * 4 + rr * 2 + 1] = v.y;
                }
            float acc[16];
#pragma unroll
            for (int q = 0; q < 16; q++) acc[q] = 0.f;
            if (s1 > 0)
                part_res(g_h1_hi + ((size_t)(s1 - 1) * BB + m0) * HH,
                         g_h1_lo + ((size_t)(s1 - 1) * BB + m0) * HH, acc);
            epi(acc, pre, c1s, g_h1_hi, g_h1_lo, s1);
        }

        if (s2 >= 0 && s2 < SS) {
            float pre[16];
#pragma unroll
            for (int g = 0; g < 4; g++)
#pragma unroll
                for (int rr = 0; rr < 2; rr++) {
                    pre[g * 4 + rr * 2 + 0] = b2r[g][0];
                    pre[g * 4 + rr * 2 + 1] = b2r[g][1];
                }
            float acc[16];
#pragma unroll
            for (int q = 0; q < 16; q++) acc[q] = 0.f;
            part_str(g_h1_hi + ((size_t)s2 * BB + m0) * HH,
                     g_h1_lo + ((size_t)s2 * BB + m0) * HH,
                     g_wih2_hi, g_wih2_lo, acc);
            if (s2 > 0)
                part_str(g_h2_hi + ((size_t)(s2 - 1) * BB + m0) * HH,
                         g_h2_lo + ((size_t)(s2 - 1) * BB + m0) * HH,
                         g_whh2_hi, g_whh2_lo, acc);
            epi(acc, pre, c2s, g_h2_hi, g_h2_lo, s2);
        }

        if (s3 >= 0 && s3 < SS) {
            float pre[16];
#pragma unroll
            for (int g = 0; g < 4; g++)
#pragma unroll
                for (int rr = 0; rr < 2; rr++) {
                    pre[g * 4 + rr * 2 + 0] = b3r[g][0];
                    pre[g * 4 + rr * 2 + 1] = b3r[g][1];
                }
            float acc[16];
#pragma unroll
            for (int q = 0; q < 16; q++) acc[q] = 0.f;
            part_str(g_h2_hi + ((size_t)s3 * BB + m0) * HH,
                     g_h2_lo + ((size_t)s3 * BB + m0) * HH,
                     g_wih3_hi, g_wih3_lo, acc);
            if (s3 > 0)
                part_str(g_h3_hi + ((size_t)(s3 - 1) * BB + m0) * HH,
                         g_h3_lo + ((size_t)(s3 - 1) * BB + m0) * HH,
                         g_whh3_hi, g_whh3_lo, acc);
            epi(acc, pre, c3s, g_h3_hi, g_h3_lo, s3);
        }

        gbar_g((unsigned)(t + 1), bbat);
    }
}

// ---------------- final FC: out[b] = h3[S-1,b,:] . fc_w + fc_b (permuted h) ----
__global__ void k_fc(const float* __restrict__ fcw, const float* __restrict__ fcb,
                     float* __restrict__ out) {
    __shared__ float red[4];
    int b = blockIdx.x, tid = threadIdx.x;
    size_t base = ((size_t)(SS - 1) * BB + b) * HH;
    float sum = 0.f;
    for (int p = tid; p < HH; p += 128) {
        int l = (p & ~15) | l16(p & 15);
        sum += (__bfloat162float(g_h3_hi[base + p]) + __bfloat162float(g_h3_lo[base + p])) * fcw[l];
    }
#pragma unroll
    for (int o = 16; o; o >>= 1) sum += __shfl_xor_sync(0xFFFFFFFFu, sum, o);
    if ((tid & 31) == 0) red[tid >> 5] = sum;
    __syncthreads();
    if (tid == 0) out[b] = red[0] + red[1] + red[2] + red[3] + fcb[0];
}

// ---------------- launch ----------------
extern "C" void kernel_launch(void* const* d_in, const int* in_sizes, int n_in,
                              void* d_out, int out_size) {
    const float* x    = (const float*)d_in[0];
    const float* wih1 = (const float*)d_in[1];
    const float* whh1 = (const float*)d_in[2];
    const float* b1   = (const float*)d_in[3];
    const float* wih2 = (const float*)d_in[4];
    const float* whh2 = (const float*)d_in[5];
    const float* b2   = (const float*)d_in[6];
    const float* wih3 = (const float*)d_in[7];
    const float* whh3 = (const float*)d_in[8];
    const float* b3   = (const float*)d_in[9];
    const float* fcw  = (const float*)d_in[10];
    const float* fcb  = (const float*)d_in[11];

    cudaFuncSetAttribute(k_wave, cudaFuncAttributeMaxDynamicSharedMemorySize, WAV_SMEM);
    cudaFuncSetAttribute(k_gemm_xw, cudaFuncAttributeMaxDynamicSharedMemorySize, XW_SMEM);

    size_t nsp = NSPLIT;
    k_split_all<<<(unsigned)((nsp + 255) / 256), 256>>>(x, wih1, whh1, wih2, whh2, wih3, whh3);
    k_bar_init<<<1, 128>>>();

    dim3 gg(G4 / XBN, (SS * BB) / XBM);
    k_gemm_xw<<<gg, 256, XW_SMEM>>>(b1);
    k_wave<<<NCTA, 256, WAV_SMEM>>>(b2, b3);
    k_fc<<<BB, 128>>>(fcw, fcb, (float*)d_out);
}

// round 14
// speedup vs baseline: 1.0214x; 1.0214x over previous
#include <cuda_runtime.h>
#include <cuda_fp16.h>
#include <cstdint>

#define SS 512
#define BB 256
#define II 64
#define HH 512
#define G4 2048
#define NCTA 128

// ---------------- static device scratch (no allocs allowed) ----------------
__device__ float   g_xw[(size_t)SS * BB * G4];      // current-layer input projection (fp32)
__device__ __half  g_h1_hi[(size_t)SS * BB * HH], g_h1_lo[(size_t)SS * BB * HH];
__device__ __half  g_h2_hi[(size_t)SS * BB * HH], g_h2_lo[(size_t)SS * BB * HH];
__device__ __half  g_h3_hi[(size_t)SS * BB * HH], g_h3_lo[(size_t)SS * BB * HH];
__device__ __half  g_x_hi[(size_t)SS * BB * II],  g_x_lo[(size_t)SS * BB * II];

__device__ __half g_wih1_hi[G4 * II], g_wih1_lo[G4 * II];
__device__ __half g_whh1_hi[G4 * HH], g_whh1_lo[G4 * HH];
__device__ __half g_wih2_hi[G4 * HH], g_wih2_lo[G4 * HH];
__device__ __half g_whh2_hi[G4 * HH], g_whh2_lo[G4 * HH];
__device__ __half g_wih3_hi[G4 * HH], g_wih3_lo[G4 * HH];
__device__ __half g_whh3_hi[G4 * HH], g_whh3_lo[G4 * HH];

// leaderless group barrier: 4 groups x 32 flags, each group = one 128B line
__device__ unsigned g_bflag[4 * 32];

// k-permutation within each 16-block: stored position q holds logical l16(q)
__device__ __forceinline__ int l16(int q) {
    return ((q >> 2) << 1) | (q & 1) | ((q & 2) << 2);
}

// ---------------- helpers ----------------
__device__ __forceinline__ void split_f16(float v, __half& hi, __half& lo) {
    hi = __float2half(v);
    lo = __float2half(v - __half2float(hi));
}

__device__ __forceinline__ void mma16816(float* d, const unsigned* a, const unsigned* b) {
    asm volatile(
        "mma.sync.aligned.m16n8k16.row.col.f32.f16.f16.f32 "
        "{%0,%1,%2,%3}, {%4,%5,%6,%7}, {%8,%9}, {%0,%1,%2,%3};\n"
        : "+f"(d[0]), "+f"(d[1]), "+f"(d[2]), "+f"(d[3])
        : "r"(a[0]), "r"(a[1]), "r"(a[2]), "r"(a[3]), "r"(b[0]), "r"(b[1]));
}

__device__ __forceinline__ unsigned smem_u32(const void* p) {
    unsigned a;
    asm("{ .reg .u64 t; cvta.to.shared.u64 t, %1; cvt.u32.u64 %0, t; }" : "=r"(a) : "l"(p));
    return a;
}

__device__ __forceinline__ void cp16(unsigned dst, const void* src) {
    asm volatile("cp.async.cg.shared.global [%0], [%1], 16;" :: "r"(dst), "l"(src));
}
__device__ __forceinline__ void cp_commit() {
    asm volatile("cp.async.commit_group;");
}
template <int N>
__device__ __forceinline__ void cp_wait() {
    asm volatile("cp.async.wait_group %0;" :: "n"(N));
}

__device__ __forceinline__ void bar_half(int half) {
    if (half == 0) asm volatile("bar.sync 1, 256;" ::: "memory");
    else           asm volatile("bar.sync 2, 256;" ::: "memory");
}

__device__ __forceinline__ float fsigmoid(float x) {
    return 1.f / (1.f + __expf(-x));
}
__device__ __forceinline__ float felu(float x) {
    return x > 0.f ? x : (__expf(x) - 1.f);
}

// leaderless group barrier: each CTA publishes its flag; 32 threads spin on all flags
__device__ __forceinline__ void gbar_g(unsigned target, int grp, int mycta) {
    __syncthreads();
    if (threadIdx.x == 0)
        asm volatile("st.release.gpu.u32 [%0], %1;"
                     :: "l"(&g_bflag[grp * 32 + mycta]), "r"(target) : "memory");
    if (threadIdx.x < 32) {
        unsigned g;
        do {
            asm volatile("ld.acquire.gpu.u32 %0, [%1];"
                         : "=r"(g) : "l"(&g_bflag[grp * 32 + threadIdx.x]) : "memory");
        } while (g < target);
    }
    __syncthreads();
}

__global__ void k_bar_init() {
    int i = threadIdx.x;
    if (i < 4 * 32) g_bflag[i] = 0;
}

// ---------------- fused split kernel (weights + x), k-permuted, fp16 ----------------
#define NW1 (G4 * II)
#define NWH (G4 * HH)
#define NX  ((size_t)SS * BB * II)
#define NSPLIT (NW1 + 5 * NWH + NX)

__global__ void k_split_all(const float* __restrict__ x,
                            const float* __restrict__ wih1, const float* __restrict__ whh1,
                            const float* __restrict__ wih2, const float* __restrict__ whh2,
                            const float* __restrict__ wih3, const float* __restrict__ whh3) {
    size_t i = (size_t)blockIdx.x * 256 + threadIdx.x;
    if (i >= NSPLIT) return;
    if (i < NW1) {
        int j = (int)i;
        int p = j % II, row = j / II;
        int l = (p & ~15) | l16(p & 15);
        split_f16(wih1[row * II + l], g_wih1_hi[j], g_wih1_lo[j]);
    } else if (i < NW1 + 5 * (size_t)NWH) {
        size_t r = i - NW1;
        int t = (int)(r >> 20);              // NWH = 2^20
        int j = (int)(r & (NWH - 1));
        int p = j % HH, row = j / HH;
        int l = (p & ~15) | l16(p & 15);
        const float* src;
        __half *hi, *lo;
        switch (t) {
            case 0: src = whh1; hi = g_whh1_hi; lo = g_whh1_lo; break;
            case 1: src = wih2; hi = g_wih2_hi; lo = g_wih2_lo; break;
            case 2: src = whh2; hi = g_whh2_hi; lo = g_whh2_lo; break;
            case 3: src = wih3; hi = g_wih3_hi; lo = g_wih3_lo; break;
            default: src = whh3; hi = g_whh3_hi; lo = g_whh3_lo; break;
        }
        split_f16(src[(size_t)row * HH + l], hi[j], lo[j]);
    } else {
        size_t j = i - (NW1 + 5 * (size_t)NWH);
        int p = (int)(j % II);
        int b = (int)((j / II) % BB);
        int s = (int)(j / ((size_t)II * BB));
        int l = (p & ~15) | l16(p & 15);
        split_f16(x[((size_t)b * SS + s) * II + l], g_x_hi[j], g_x_lo[j]);
    }
}

// ---------------- layer-1 xw GEMM (K=64, 3-pass, proven body) ----------------
#define XBM 128
#define XBN 128
#define XBK 32
#define XST 4
#define XAP 40
#define X1_SMEM (XST * (XBM + XBN) * XAP * 2 * 2)   // 163840

__global__ __launch_bounds__(256) void k_gemm_x1(const float* __restrict__ bias) {
    const __half *Ah = g_x_hi, *Al = g_x_lo, *Wh = g_wih1_hi, *Wl = g_wih1_lo;
    const int K = II;

    extern __shared__ char xsm[];
    __half* sAh = (__half*)xsm;
    __half* sAl = sAh + XST * XBM * XAP;
    __half* sWh = sAl + XST * XBM * XAP;
    __half* sWl = sWh + XST * XBN * XAP;

    unsigned uAh = smem_u32(sAh), uAl = smem_u32(sAl);
    unsigned uWh = smem_u32(sWh), uWl = smem_u32(sWl);

    int tid = threadIdx.x;
    int m0 = blockIdx.y * XBM;
    int n0 = blockIdx.x * XBN;
    int warp = tid >> 5, lane = tid & 31;
    int wm = warp >> 1, wn = warp & 1;
    int gq = lane >> 2, tg = lane & 3;

    int lrow = tid >> 1;
    int lcol = (tid & 1) * 16;

    float acc[2][8][4];
#pragma unroll
    for (int mi = 0; mi < 2; mi++)
#pragma unroll
        for (int ni = 0; ni < 8; ni++)
#pragma unroll
            for (int r = 0; r < 4; r++) acc[mi][ni][r] = 0.f;

    int nkt = K / XBK;   // 2

    auto issue = [&](int kt, int st) {
        size_t ga = (size_t)(m0 + lrow) * K + kt * XBK + lcol;
        size_t gw = (size_t)(n0 + lrow) * K + kt * XBK + lcol;
        unsigned da = (unsigned)(((st * XBM + lrow) * XAP + lcol) * 2);
        unsigned dw = (unsigned)(((st * XBN + lrow) * XAP + lcol) * 2);
        cp16(uAh + da, Ah + ga);       cp16(uAh + da + 16, Ah + ga + 8);
        cp16(uAl + da, Al + ga);       cp16(uAl + da + 16, Al + ga + 8);
        cp16(uWh + dw, Wh + gw);       cp16(uWh + dw + 16, Wh + gw + 8);
        cp16(uWl + dw, Wl + gw);       cp16(uWl + dw + 16, Wl + gw + 8);
        cp_commit();
    };

    int npro = nkt < (XST - 1) ? nkt : (XST - 1);
    for (int p = 0; p < npro; p++) issue(p, p);

    for (int kt = 0; kt < nkt; kt++) {
        int rem = nkt - kt - 1;
        if (rem >= 2) cp_wait<2>();
        else if (rem == 1) cp_wait<1>();
        else cp_wait<0>();
        __syncthreads();

        if (kt + XST - 1 < nkt) issue(kt + XST - 1, (kt + XST - 1) % XST);

        int st = kt % XST;
        const __half* cAh = sAh + st * XBM * XAP;
        const __half* cAl = sAl + st * XBM * XAP;
        const __half* cWh = sWh + st * XBN * XAP;
        const __half* cWl = sWl + st * XBN * XAP;

#pragma unroll
        for (int kc = 0; kc < XBK; kc += 16) {
            unsigned ah[2][4], al[2][4], bh[8][2], bl[8][2];
#pragma unroll
            for (int mi = 0; mi < 2; mi++) {
                int r = wm * 32 + mi * 16 + gq;
                ah[mi][0] = *(unsigned*)&cAh[r * XAP + kc + 2 * tg];
                ah[mi][1] = *(unsigned*)&cAh[(r + 8) * XAP + kc + 2 * tg];
                ah[mi][2] = *(unsigned*)&cAh[r * XAP + kc + 2 * tg + 8];
                ah[mi][3] = *(unsigned*)&cAh[(r + 8) * XAP + kc + 2 * tg + 8];
                al[mi][0] = *(unsigned*)&cAl[r * XAP + kc + 2 * tg];
                al[mi][1] = *(unsigned*)&cAl[(r + 8) * XAP + kc + 2 * tg];
                al[mi][2] = *(unsigned*)&cAl[r * XAP + kc + 2 * tg + 8];
                al[mi][3] = *(unsigned*)&cAl[(r + 8) * XAP + kc + 2 * tg + 8];
            }
#pragma unroll
            for (int ni = 0; ni < 8; ni++) {
                int n = wn * 64 + ni * 8 + gq;
                bh[ni][0] = *(unsigned*)&cWh[n * XAP + kc + 2 * tg];
                bh[ni][1] = *(unsigned*)&cWh[n * XAP + kc + 2 * tg + 8];
                bl[ni][0] = *(unsigned*)&cWl[n * XAP + kc + 2 * tg];
                bl[ni][1] = *(unsigned*)&cWl[n * XAP + kc + 2 * tg + 8];
            }
#pragma unroll
            for (int mi = 0; mi < 2; mi++)
#pragma unroll
                for (int ni = 0; ni < 8; ni++) {
                    mma16816(acc[mi][ni], ah[mi], bh[ni]);
                    mma16816(acc[mi][ni], ah[mi], bl[ni]);
                    mma16816(acc[mi][ni], al[mi], bh[ni]);
                }
        }
    }

#pragma unroll
    for (int mi = 0; mi < 2; mi++)
#pragma unroll
        for (int ni = 0; ni < 8; ni++) {
            int row = m0 + wm * 32 + mi * 16 + gq;
            int col = n0 + wn * 64 + ni * 8 + 2 * tg;
            float b0v = bias[col], b1v = bias[col + 1];
            g_xw[(size_t)row * G4 + col]           = acc[mi][ni][0] + b0v;
            g_xw[(size_t)row * G4 + col + 1]       = acc[mi][ni][1] + b1v;
            g_xw[(size_t)(row + 8) * G4 + col]     = acc[mi][ni][2] + b0v;
            g_xw[(size_t)(row + 8) * G4 + col + 1] = acc[mi][ni][3] + b1v;
        }
}

// ---------------- xw GEMM for layers 2/3: A = h_hi (2-pass), K=512 ----------------
// POINTERS RESOLVED DEVICE-SIDE (host cannot take addresses of __device__ globals).
#define XH_SMEM (3 * XST * XBM * XAP * 2)   // 122880 (A, Wh, Wl)

__global__ __launch_bounds__(256) void k_gemm_h(int layer, const float* __restrict__ bias) {
    const __half *Ah, *Wh, *Wl;
    if (layer == 1) { Ah = g_h1_hi; Wh = g_wih2_hi; Wl = g_wih2_lo; }
    else            { Ah = g_h2_hi; Wh = g_wih3_hi; Wl = g_wih3_lo; }
    const int K = HH;

    extern __shared__ char xsm[];
    __half* sAh = (__half*)xsm;
    __half* sWh = sAh + XST * XBM * XAP;
    __half* sWl = sWh + XST * XBN * XAP;

    unsigned uAh = smem_u32(sAh), uWh = smem_u32(sWh), uWl = smem_u32(sWl);

    int tid = threadIdx.x;
    int m0 = blockIdx.y * XBM;
    int n0 = blockIdx.x * XBN;
    int warp = tid >> 5, lane = tid & 31;
    int wm = warp >> 1, wn = warp & 1;
    int gq = lane >> 2, tg = lane & 3;

    int lrow = tid >> 1;
    int lcol = (tid & 1) * 16;

    float acc[2][8][4];
#pragma unroll
    for (int mi = 0; mi < 2; mi++)
#pragma unroll
        for (int ni = 0; ni < 8; ni++)
#pragma unroll
            for (int r = 0; r < 4; r++) acc[mi][ni][r] = 0.f;

    int nkt = K / XBK;   // 16

    auto issue = [&](int kt, int st) {
        size_t ga = (size_t)(m0 + lrow) * K + kt * XBK + lcol;
        size_t gw = (size_t)(n0 + lrow) * K + kt * XBK + lcol;
        unsigned da = (unsigned)(((st * XBM + lrow) * XAP + lcol) * 2);
        cp16(uAh + da, Ah + ga);       cp16(uAh + da + 16, Ah + ga + 8);
        cp16(uWh + da, Wh + gw);       cp16(uWh + da + 16, Wh + gw + 8);
        cp16(uWl + da, Wl + gw);       cp16(uWl + da + 16, Wl + gw + 8);
        cp_commit();
    };

    for (int p = 0; p < XST - 1; p++) issue(p, p);

    for (int kt = 0; kt < nkt; kt++) {
        int rem = nkt - kt - 1;
        if (rem >= 2) cp_wait<2>();
        else if (rem == 1) cp_wait<1>();
        else cp_wait<0>();
        __syncthreads();

        if (kt + XST - 1 < nkt) issue(kt + XST - 1, (kt + XST - 1) % XST);

        int st = kt % XST;
        const __half* cAh = sAh + st * XBM * XAP;
        const __half* cWh = sWh + st * XBN * XAP;
        const __half* cWl = sWl + st * XBN * XAP;

#pragma unroll
        for (int kc = 0; kc < XBK; kc += 16) {
            unsigned ah[2][4], bh[8][2], bl[8][2];
#pragma unroll
            for (int mi = 0; mi < 2; mi++) {
                int r = wm * 32 + mi * 16 + gq;
                ah[mi][0] = *(unsigned*)&cAh[r * XAP + kc + 2 * tg];
                ah[mi][1] = *(unsigned*)&cAh[(r + 8) * XAP + kc + 2 * tg];
                ah[mi][2] = *(unsigned*)&cAh[r * XAP + kc + 2 * tg + 8];
                ah[mi][3] = *(unsigned*)&cAh[(r + 8) * XAP + kc + 2 * tg + 8];
            }
#pragma unroll
            for (int ni = 0; ni < 8; ni++) {
                int n = wn * 64 + ni * 8 + gq;
                bh[ni][0] = *(unsigned*)&cWh[n * XAP + kc + 2 * tg];
                bh[ni][1] = *(unsigned*)&cWh[n * XAP + kc + 2 * tg + 8];
                bl[ni][0] = *(unsigned*)&cWl[n * XAP + kc + 2 * tg];
                bl[ni][1] = *(unsigned*)&cWl[n * XAP + kc + 2 * tg + 8];
            }
#pragma unroll
            for (int mi = 0; mi < 2; mi++)
#pragma unroll
                for (int ni = 0; ni < 8; ni++) {
                    mma16816(acc[mi][ni], ah[mi], bh[ni]);
                    mma16816(acc[mi][ni], ah[mi], bl[ni]);
                }
        }
    }

#pragma unroll
    for (int mi = 0; mi < 2; mi++)
#pragma unroll
        for (int ni = 0; ni < 8; ni++) {
            int row = m0 + wm * 32 + mi * 16 + gq;
            int col = n0 + wn * 64 + ni * 8 + 2 * tg;
            float b0v = bias[col], b1v = bias[col + 1];
            g_xw[(size_t)row * G4 + col]           = acc[mi][ni][0] + b0v;
            g_xw[(size_t)row * G4 + col + 1]       = acc[mi][ni][1] + b1v;
            g_xw[(size_t)(row + 8) * G4 + col]     = acc[mi][ni][2] + b0v;
            g_xw[(size_t)(row + 8) * G4 + col + 1] = acc[mi][ni][3] + b1v;
        }
}

// ---------------- persistent recurrent kernel: split-K, fp16 2-pass ----------------
// 128 CTAs x 512 threads. Half h computes 64x64 tile over K[h*256, h*256+256),
// 4 k-tiles each, h_hi only, double buffer, PROVEN order: wait -> bar -> issue -> consume.
// SMEM: sWh 64x528 (67584) | sWl (67584) | half0 2x10240 | half1 2x10240 | red 17408
#define SMEM_REC 193536
#define SWP 528
#define STP 80
#define RKT 64
#define HB_OFF 135168
#define RED_OFF 176128
#define REDP 68

__global__ __launch_bounds__(512, 1) void k_rec(int layer) {
    extern __shared__ char sm[];
    __half (*sWh)[SWP] = (__half(*)[SWP])(sm);
    __half (*sWl)[SWP] = (__half(*)[SWP])(sm + 67584);
    float* red = (float*)(sm + RED_OFF);

    const __half *Whg, *Wlg;
    __half *HOhi, *HOlo;
    if (layer == 0)      { Whg = g_whh1_hi; Wlg = g_whh1_lo; HOhi = g_h1_hi; HOlo = g_h1_lo; }
    else if (layer == 1) { Whg = g_whh2_hi; Wlg = g_whh2_lo; HOhi = g_h2_hi; HOlo = g_h2_lo; }
    else                 { Whg = g_whh3_hi; Wlg = g_whh3_lo; HOhi = g_h3_hi; HOlo = g_h3_lo; }

    int tid = threadIdx.x;
    int half = tid >> 8;
    int htid = tid & 255;
    int lane = tid & 31;
    int hw = htid >> 5;
    int bx = blockIdx.x;
    int bhid = bx >> 2;
    int bbat = bx & 3;
    int m0 = bbat * 64;
    int n0 = bhid * 16;
    int wm = hw >> 1, wn = hw & 1;
    int gq = lane >> 2, tg = lane & 3;
    int koff = half * 256;

    // resident W slice (hi+lo)
    for (int idx = tid; idx < 64 * 256; idx += 512) {
        int r = idx >> 8;
        int c = (idx & 255) * 2;
        int grow = (r >> 4) * HH + n0 + (r & 15);
        size_t gi = (size_t)grow * HH + c;
        *(unsigned*)&sWh[r][c] = *(const unsigned*)&Whg[gi];
        *(unsigned*)&sWl[r][c] = *(const unsigned*)&Wlg[gi];
    }
    __syncthreads();

    unsigned hb = smem_u32(sm) + HB_OFF + (unsigned)half * 20480u;
    int lrow = htid >> 2;             // 64 rows, 4 threads/row
    int lcol = (htid & 3) * 16;

    int row0 = wm * 16 + gq;
    int jloc = wn * 8 + 2 * tg;
    int jst  = 4 * tg + 2 * wn;

    unsigned base_t = (unsigned)layer * SS;

    float cb[2][2] = {{0.f, 0.f}, {0.f, 0.f}};
    float xwn[4][2][2];
    if (half == 0) {
        const float* xwb = g_xw + ((size_t)0 * BB + m0 + row0) * G4;
#pragma unroll
        for (int g = 0; g < 4; g++)
#pragma unroll
            for (int rr = 0; rr < 2; rr++) {
                float2 v = *(const float2*)(xwb + (size_t)rr * 8 * G4 + g * HH + n0 + jloc);
                xwn[g][rr][0] = v.x; xwn[g][rr][1] = v.y;
            }
    }

    for (int s = 0; s < SS; s++) {
        float acc[4][4];
#pragma unroll
        for (int g = 0; g < 4; g++)
#pragma unroll
            for (int r = 0; r < 4; r++) acc[g][r] = 0.f;

        if (s > 0) {
            const __half* Hh = HOhi + ((size_t)(s - 1) * BB + m0) * HH;

            auto issueH = [&](int kt) {
                int b = kt & 1;
                const __half* gh = Hh + (size_t)lrow * HH + koff + kt * RKT + lcol;
                unsigned d = (unsigned)(b * 10240 + (lrow * STP + lcol) * 2);
                cp16(hb + d, gh);  cp16(hb + d + 16, gh + 8);
                cp_commit();
            };

            issueH(0);
#pragma unroll
            for (int kt = 0; kt < 4; kt++) {
                cp_wait<0>();                     // tile kt landed (this thread's copies)
                bar_half(half);                   // all threads' copies visible; prev buffer free
                if (kt + 1 < 4) issueH(kt + 1);

                int b = kt & 1;
                const __half* cHh = (const __half*)(sm + HB_OFF + half * 20480 + b * 10240);
#pragma unroll
                for (int kc = 0; kc < RKT; kc += 16) {
                    int kw = koff + kt * RKT + kc;
                    unsigned ah[4], bh[4][2], bl[4][2];
                    uint2 t;
                    t = *(uint2*)&cHh[row0 * STP + kc + 4 * tg];        ah[0] = t.x; ah[2] = t.y;
                    t = *(uint2*)&cHh[(row0 + 8) * STP + kc + 4 * tg];  ah[1] = t.x; ah[3] = t.y;
#pragma unroll
                    for (int g = 0; g < 4; g++) {
                        int n = g * 16 + wn * 8 + gq;
                        t = *(uint2*)&sWh[n][kw + 4 * tg];  bh[g][0] = t.x; bh[g][1] = t.y;
                        t = *(uint2*)&sWl[n][kw + 4 * tg];  bl[g][0] = t.x; bl[g][1] = t.y;
                    }
#pragma unroll
                    for (int g = 0; g < 4; g++) {
                        mma16816(acc[g], ah, bh[g]);
                        mma16816(acc[g], ah, bl[g]);
                    }
                }
            }
        }

        // ---- cross-half reduction ----
        __syncthreads();
        if (s > 0) {
            if (half == 1) {
#pragma unroll
                for (int g = 0; g < 4; g++)
#pragma unroll
                    for (int rr = 0; rr < 2; rr++)
#pragma unroll
                        for (int cc = 0; cc < 2; cc++)
                            red[(row0 + rr * 8) * REDP + g * 16 + jloc + cc] = acc[g][rr * 2 + cc];
            }
            __syncthreads();
            if (half == 0) {
#pragma unroll
                for (int g = 0; g < 4; g++)
#pragma unroll
                    for (int rr = 0; rr < 2; rr++)
#pragma unroll
                        for (int cc = 0; cc < 2; cc++)
                            acc[g][rr * 2 + cc] += red[(row0 + rr * 8) * REDP + g * 16 + jloc + cc];
            }
        }

        if (half == 0) {
            float xwf[4][2][2];
#pragma unroll
            for (int g = 0; g < 4; g++)
#pragma unroll
                for (int rr = 0; rr < 2; rr++) {
                    xwf[g][rr][0] = xwn[g][rr][0];
                    xwf[g][rr][1] = xwn[g][rr][1];
                }
            if (s + 1 < SS) {
                const float* xwb = g_xw + ((size_t)(s + 1) * BB + m0 + row0) * G4;
#pragma unroll
                for (int g = 0; g < 4; g++)
#pragma unroll
                    for (int rr = 0; rr < 2; rr++) {
                        float2 v = *(const float2*)(xwb + (size_t)rr * 8 * G4 + g * HH + n0 + jloc);
                        xwn[g][rr][0] = v.x; xwn[g][rr][1] = v.y;
                    }
            }

#pragma unroll
            for (int rr = 0; rr < 2; rr++) {
                __half hh[2], hl[2];
#pragma unroll
                for (int cc = 0; cc < 2; cc++) {
                    int fi = rr * 2 + cc;
                    float pi = acc[0][fi] + xwf[0][rr][cc];
                    float pf = acc[1][fi] + xwf[1][rr][cc];
                    float pg = acc[2][fi] + xwf[2][rr][cc];
                    float po = acc[3][fi] + xwf[3][rr][cc];
                    float iv = fsigmoid(pi);
                    float fv = fsigmoid(pf);
                    float gv = felu(pg);
                    float ov = fsigmoid(po);
                    float cn = fv * cb[rr][cc] + iv * gv;
                    float hv = ov * felu(cn);
                    cb[rr][cc] = cn;
                    split_f16(hv, hh[cc], hl[cc]);
                }
                size_t hidx = ((size_t)s * BB + m0 + row0 + rr * 8) * HH + n0 + jst;
                *(unsigned*)(HOhi + hidx) = *(unsigned*)hh;
                *(unsigned*)(HOlo + hidx) = *(unsigned*)hl;
            }
        }

        gbar_g(base_t + (unsigned)s + 1u, bbat, bhid);
    }
}

// ---------------- final FC: out[b] = h3[S-1,b,:] . fc_w + fc_b (hi+lo, permuted) ----
__global__ void k_fc(const float* __restrict__ fcw, const float* __restrict__ fcb,
                     float* __restrict__ out) {
    __shared__ float red[4];
    int b = blockIdx.x, tid = threadIdx.x;
    size_t base = ((size_t)(SS - 1) * BB + b) * HH;
    float sum = 0.f;
    for (int p = tid; p < HH; p += 128) {
        int l = (p & ~15) | l16(p & 15);
        sum += (__half2float(g_h3_hi[base + p]) + __half2float(g_h3_lo[base + p])) * fcw[l];
    }
#pragma unroll
    for (int o = 16; o; o >>= 1) sum += __shfl_xor_sync(0xFFFFFFFFu, sum, o);
    if ((tid & 31) == 0) red[tid >> 5] = sum;
    __syncthreads();
    if (tid == 0) out[b] = red[0] + red[1] + red[2] + red[3] + fcb[0];
}

// ---------------- launch ----------------
extern "C" void kernel_launch(void* const* d_in, const int* in_sizes, int n_in,
                              void* d_out, int out_size) {
    const float* x    = (const float*)d_in[0];
    const float* wih1 = (const float*)d_in[1];
    const float* whh1 = (const float*)d_in[2];
    const float* b1   = (const float*)d_in[3];
    const float* wih2 = (const float*)d_in[4];
    const float* whh2 = (const float*)d_in[5];
    const float* b2   = (const float*)d_in[6];
    const float* wih3 = (const float*)d_in[7];
    const float* whh3 = (const float*)d_in[8];
    const float* b3   = (const float*)d_in[9];
    const float* fcw  = (const float*)d_in[10];
    const float* fcb  = (const float*)d_in[11];

    cudaFuncSetAttribute(k_rec, cudaFuncAttributeMaxDynamicSharedMemorySize, SMEM_REC);
    cudaFuncSetAttribute(k_gemm_x1, cudaFuncAttributeMaxDynamicSharedMemorySize, X1_SMEM);
    cudaFuncSetAttribute(k_gemm_h, cudaFuncAttributeMaxDynamicSharedMemorySize, XH_SMEM);

    // 0 split, 1 barinit, 2 gemm_x1, 3 rec0, 4 gemm_h, 5 rec1 (ncu -s 5), 6 gemm_h, 7 rec2, 8 fc
    size_t nsp = NSPLIT;
    k_split_all<<<(unsigned)((nsp + 255) / 256), 256>>>(x, wih1, whh1, wih2, whh2, wih3, whh3);
    k_bar_init<<<1, 128>>>();

    dim3 gg(G4 / XBN, (SS * BB) / XBM);
    k_gemm_x1<<<gg, 256, X1_SMEM>>>(b1);
    k_rec<<<NCTA, 512, SMEM_REC>>>(0);
    k_gemm_h<<<gg, 256, XH_SMEM>>>(1, b2);
    k_rec<<<NCTA, 512, SMEM_REC>>>(1);
    k_gemm_h<<<gg, 256, XH_SMEM>>>(2, b3);
    k_rec<<<NCTA, 512, SMEM_REC>>>(2);
    k_fc<<<BB, 128>>>(fcw, fcb, (float*)d_out);
}

// round 15
// speedup vs baseline: 1.4113x; 1.3818x over previous
#include <cuda_runtime.h>
#include <cuda_fp16.h>
#include <cstdint>

#define SS 512
#define BB 256
#define II 64
#define HH 512
#define G4 2048
#define NCTA 128

// ---------------- static device scratch (no allocs allowed) ----------------
__device__ float   g_xw[(size_t)SS * BB * G4];      // current-layer input projection (fp32)
__device__ __half  g_h1_hi[(size_t)SS * BB * HH], g_h1_lo[(size_t)SS * BB * HH];
__device__ __half  g_h2_hi[(size_t)SS * BB * HH], g_h2_lo[(size_t)SS * BB * HH];
__device__ __half  g_h3_hi[(size_t)SS * BB * HH], g_h3_lo[(size_t)SS * BB * HH];
__device__ __half  g_x_hi[(size_t)SS * BB * II],  g_x_lo[(size_t)SS * BB * II];

__device__ __half g_wih1_hi[G4 * II], g_wih1_lo[G4 * II];
__device__ __half g_whh1_hi[G4 * HH], g_whh1_lo[G4 * HH];
__device__ __half g_wih2_hi[G4 * HH], g_wih2_lo[G4 * HH];
__device__ __half g_whh2_hi[G4 * HH], g_whh2_lo[G4 * HH];
__device__ __half g_wih3_hi[G4 * HH], g_wih3_lo[G4 * HH];
__device__ __half g_whh3_hi[G4 * HH], g_whh3_lo[G4 * HH];

// leader-based group barriers (round-9 proven): 4 groups, each on its own 128B line
__device__ unsigned g_bcnt[4 * 32];
__device__ unsigned g_bgen[4 * 32];

// k-permutation within each 16-block: stored position q holds logical l16(q)
__device__ __forceinline__ int l16(int q) {
    return ((q >> 2) << 1) | (q & 1) | ((q & 2) << 2);
}

// ---------------- helpers ----------------
__device__ __forceinline__ void split_f16(float v, __half& hi, __half& lo) {
    hi = __float2half(v);
    lo = __float2half(v - __half2float(hi));
}

__device__ __forceinline__ void mma16816(float* d, const unsigned* a, const unsigned* b) {
    asm volatile(
        "mma.sync.aligned.m16n8k16.row.col.f32.f16.f16.f32 "
        "{%0,%1,%2,%3}, {%4,%5,%6,%7}, {%8,%9}, {%0,%1,%2,%3};\n"
        : "+f"(d[0]), "+f"(d[1]), "+f"(d[2]), "+f"(d[3])
        : "r"(a[0]), "r"(a[1]), "r"(a[2]), "r"(a[3]), "r"(b[0]), "r"(b[1]));
}

__device__ __forceinline__ unsigned smem_u32(const void* p) {
    unsigned a;
    asm("{ .reg .u64 t; cvta.to.shared.u64 t, %1; cvt.u32.u64 %0, t; }" : "=r"(a) : "l"(p));
    return a;
}

__device__ __forceinline__ void cp16(unsigned dst, const void* src) {
    asm volatile("cp.async.cg.shared.global [%0], [%1], 16;" :: "r"(dst), "l"(src));
}
__device__ __forceinline__ void cp_commit() {
    asm volatile("cp.async.commit_group;");
}
template <int N>
__device__ __forceinline__ void cp_wait() {
    asm volatile("cp.async.wait_group %0;" :: "n"(N));
}

__device__ __forceinline__ void bar_half(int half) {
    if (half == 0) asm volatile("bar.sync 1, 256;" ::: "memory");
    else           asm volatile("bar.sync 2, 256;" ::: "memory");
}

__device__ __forceinline__ float fsigmoid(float x) {
    return 1.f / (1.f + __expf(-x));
}
__device__ __forceinline__ float felu(float x) {
    return x > 0.f ? x : (__expf(x) - 1.f);
}

// leader-based group barrier (round-9 proven): 32 CTAs of one batch group
__device__ __forceinline__ void gbar_g(unsigned target, int grp) {
    __syncthreads();
    if (threadIdx.x == 0) {
        unsigned* cnt = &g_bcnt[grp * 32];
        unsigned* gen = &g_bgen[grp * 32];
        __threadfence();
        if (atomicAdd(cnt, 1u) == 31u) {
            *cnt = 0;
            __threadfence();
            atomicExch(gen, target);
        } else {
            unsigned g;
            do {
                asm volatile("ld.global.acquire.gpu.u32 %0, [%1];" : "=r"(g) : "l"(gen));
            } while (g < target);
        }
    }
    __syncthreads();
}

__global__ void k_bar_init() {
    int i = threadIdx.x;
    if (i < 4 * 32) { g_bcnt[i] = 0; g_bgen[i] = 0; }
}

// ---------------- fused split kernel (weights + x), k-permuted, fp16 ----------------
#define NW1 (G4 * II)
#define NWH (G4 * HH)
#define NX  ((size_t)SS * BB * II)
#define NSPLIT (NW1 + 5 * NWH + NX)

__global__ void k_split_all(const float* __restrict__ x,
                            const float* __restrict__ wih1, const float* __restrict__ whh1,
                            const float* __restrict__ wih2, const float* __restrict__ whh2,
                            const float* __restrict__ wih3, const float* __restrict__ whh3) {
    size_t i = (size_t)blockIdx.x * 256 + threadIdx.x;
    if (i >= NSPLIT) return;
    if (i < NW1) {
        int j = (int)i;
        int p = j % II, row = j / II;
        int l = (p & ~15) | l16(p & 15);
        split_f16(wih1[row * II + l], g_wih1_hi[j], g_wih1_lo[j]);
    } else if (i < NW1 + 5 * (size_t)NWH) {
        size_t r = i - NW1;
        int t = (int)(r >> 20);              // NWH = 2^20
        int j = (int)(r & (NWH - 1));
        int p = j % HH, row = j / HH;
        int l = (p & ~15) | l16(p & 15);
        const float* src;
        __half *hi, *lo;
        switch (t) {
            case 0: src = whh1; hi = g_whh1_hi; lo = g_whh1_lo; break;
            case 1: src = wih2; hi = g_wih2_hi; lo = g_wih2_lo; break;
            case 2: src = whh2; hi = g_whh2_hi; lo = g_whh2_lo; break;
            case 3: src = wih3; hi = g_wih3_hi; lo = g_wih3_lo; break;
            default: src = whh3; hi = g_whh3_hi; lo = g_whh3_lo; break;
        }
        split_f16(src[(size_t)row * HH + l], hi[j], lo[j]);
    } else {
        size_t j = i - (NW1 + 5 * (size_t)NWH);
        int p = (int)(j % II);
        int b = (int)((j / II) % BB);
        int s = (int)(j / ((size_t)II * BB));
        int l = (p & ~15) | l16(p & 15);
        split_f16(x[((size_t)b * SS + s) * II + l], g_x_hi[j], g_x_lo[j]);
    }
}

// ---------------- layer-1 xw GEMM (K=64, 3-pass, proven body) ----------------
#define XBM 128
#define XBN 128
#define XBK 32
#define XST 4
#define XAP 40
#define X1_SMEM (XST * (XBM + XBN) * XAP * 2 * 2)   // 163840

__global__ __launch_bounds__(256) void k_gemm_x1(const float* __restrict__ bias) {
    const __half *Ah = g_x_hi, *Al = g_x_lo, *Wh = g_wih1_hi, *Wl = g_wih1_lo;
    const int K = II;

    extern __shared__ char xsm[];
    __half* sAh = (__half*)xsm;
    __half* sAl = sAh + XST * XBM * XAP;
    __half* sWh = sAl + XST * XBM * XAP;
    __half* sWl = sWh + XST * XBN * XAP;

    unsigned uAh = smem_u32(sAh), uAl = smem_u32(sAl);
    unsigned uWh = smem_u32(sWh), uWl = smem_u32(sWl);

    int tid = threadIdx.x;
    int m0 = blockIdx.y * XBM;
    int n0 = blockIdx.x * XBN;
    int warp = tid >> 5, lane = tid & 31;
    int wm = warp >> 1, wn = warp & 1;
    int gq = lane >> 2, tg = lane & 3;

    int lrow = tid >> 1;
    int lcol = (tid & 1) * 16;

    float acc[2][8][4];
#pragma unroll
    for (int mi = 0; mi < 2; mi++)
#pragma unroll
        for (int ni = 0; ni < 8; ni++)
#pragma unroll
            for (int r = 0; r < 4; r++) acc[mi][ni][r] = 0.f;

    int nkt = K / XBK;   // 2

    auto issue = [&](int kt, int st) {
        size_t ga = (size_t)(m0 + lrow) * K + kt * XBK + lcol;
        size_t gw = (size_t)(n0 + lrow) * K + kt * XBK + lcol;
        unsigned da = (unsigned)(((st * XBM + lrow) * XAP + lcol) * 2);
        unsigned dw = (unsigned)(((st * XBN + lrow) * XAP + lcol) * 2);
        cp16(uAh + da, Ah + ga);       cp16(uAh + da + 16, Ah + ga + 8);
        cp16(uAl + da, Al + ga);       cp16(uAl + da + 16, Al + ga + 8);
        cp16(uWh + dw, Wh + gw);       cp16(uWh + dw + 16, Wh + gw + 8);
        cp16(uWl + dw, Wl + gw);       cp16(uWl + dw + 16, Wl + gw + 8);
        cp_commit();
    };

    int npro = nkt < (XST - 1) ? nkt : (XST - 1);
    for (int p = 0; p < npro; p++) issue(p, p);

    for (int kt = 0; kt < nkt; kt++) {
        int rem = nkt - kt - 1;
        if (rem >= 2) cp_wait<2>();
        else if (rem == 1) cp_wait<1>();
        else cp_wait<0>();
        __syncthreads();

        if (kt + XST - 1 < nkt) issue(kt + XST - 1, (kt + XST - 1) % XST);

        int st = kt % XST;
        const __half* cAh = sAh + st * XBM * XAP;
        const __half* cAl = sAl + st * XBM * XAP;
        const __half* cWh = sWh + st * XBN * XAP;
        const __half* cWl = sWl + st * XBN * XAP;

#pragma unroll
        for (int kc = 0; kc < XBK; kc += 16) {
            unsigned ah[2][4], al[2][4], bh[8][2], bl[8][2];
#pragma unroll
            for (int mi = 0; mi < 2; mi++) {
                int r = wm * 32 + mi * 16 + gq;
                ah[mi][0] = *(unsigned*)&cAh[r * XAP + kc + 2 * tg];
                ah[mi][1] = *(unsigned*)&cAh[(r + 8) * XAP + kc + 2 * tg];
                ah[mi][2] = *(unsigned*)&cAh[r * XAP + kc + 2 * tg + 8];
                ah[mi][3] = *(unsigned*)&cAh[(r + 8) * XAP + kc + 2 * tg + 8];
                al[mi][0] = *(unsigned*)&cAl[r * XAP + kc + 2 * tg];
                al[mi][1] = *(unsigned*)&cAl[(r + 8) * XAP + kc + 2 * tg];
                al[mi][2] = *(unsigned*)&cAl[r * XAP + kc + 2 * tg + 8];
                al[mi][3] = *(unsigned*)&cAl[(r + 8) * XAP + kc + 2 * tg + 8];
            }
#pragma unroll
            for (int ni = 0; ni < 8; ni++) {
                int n = wn * 64 + ni * 8 + gq;
                bh[ni][0] = *(unsigned*)&cWh[n * XAP + kc + 2 * tg];
                bh[ni][1] = *(unsigned*)&cWh[n * XAP + kc + 2 * tg + 8];
                bl[ni][0] = *(unsigned*)&cWl[n * XAP + kc + 2 * tg];
                bl[ni][1] = *(unsigned*)&cWl[n * XAP + kc + 2 * tg + 8];
            }
#pragma unroll
            for (int mi = 0; mi < 2; mi++)
#pragma unroll
                for (int ni = 0; ni < 8; ni++) {
                    mma16816(acc[mi][ni], ah[mi], bh[ni]);
                    mma16816(acc[mi][ni], ah[mi], bl[ni]);
                    mma16816(acc[mi][ni], al[mi], bh[ni]);
                }
        }
    }

#pragma unroll
    for (int mi = 0; mi < 2; mi++)
#pragma unroll
        for (int ni = 0; ni < 8; ni++) {
            int row = m0 + wm * 32 + mi * 16 + gq;
            int col = n0 + wn * 64 + ni * 8 + 2 * tg;
            float b0v = bias[col], b1v = bias[col + 1];
            g_xw[(size_t)row * G4 + col]           = acc[mi][ni][0] + b0v;
            g_xw[(size_t)row * G4 + col + 1]       = acc[mi][ni][1] + b1v;
            g_xw[(size_t)(row + 8) * G4 + col]     = acc[mi][ni][2] + b0v;
            g_xw[(size_t)(row + 8) * G4 + col + 1] = acc[mi][ni][3] + b1v;
        }
}

// ---------------- xw GEMM for layers 2/3: A = h_hi (2-pass), K=512 ----------------
#define XH_SMEM (3 * XST * XBM * XAP * 2)   // 122880 (A, Wh, Wl)

__global__ __launch_bounds__(256) void k_gemm_h(int layer, const float* __restrict__ bias) {
    const __half *Ah, *Wh, *Wl;
    if (layer == 1) { Ah = g_h1_hi; Wh = g_wih2_hi; Wl = g_wih2_lo; }
    else            { Ah = g_h2_hi; Wh = g_wih3_hi; Wl = g_wih3_lo; }
    const int K = HH;

    extern __shared__ char xsm[];
    __half* sAh = (__half*)xsm;
    __half* sWh = sAh + XST * XBM * XAP;
    __half* sWl = sWh + XST * XBN * XAP;

    unsigned uAh = smem_u32(sAh), uWh = smem_u32(sWh), uWl = smem_u32(sWl);

    int tid = threadIdx.x;
    int m0 = blockIdx.y * XBM;
    int n0 = blockIdx.x * XBN;
    int warp = tid >> 5, lane = tid & 31;
    int wm = warp >> 1, wn = warp & 1;
    int gq = lane >> 2, tg = lane & 3;

    int lrow = tid >> 1;
    int lcol = (tid & 1) * 16;

    float acc[2][8][4];
#pragma unroll
    for (int mi = 0; mi < 2; mi++)
#pragma unroll
        for (int ni = 0; ni < 8; ni++)
#pragma unroll
            for (int r = 0; r < 4; r++) acc[mi][ni][r] = 0.f;

    int nkt = K / XBK;   // 16

    auto issue = [&](int kt, int st) {
        size_t ga = (size_t)(m0 + lrow) * K + kt * XBK + lcol;
        size_t gw = (size_t)(n0 + lrow) * K + kt * XBK + lcol;
        unsigned da = (unsigned)(((st * XBM + lrow) * XAP + lcol) * 2);
        cp16(uAh + da, Ah + ga);       cp16(uAh + da + 16, Ah + ga + 8);
        cp16(uWh + da, Wh + gw);       cp16(uWh + da + 16, Wh + gw + 8);
        cp16(uWl + da, Wl + gw);       cp16(uWl + da + 16, Wl + gw + 8);
        cp_commit();
    };

    for (int p = 0; p < XST - 1; p++) issue(p, p);

    for (int kt = 0; kt < nkt; kt++) {
        int rem = nkt - kt - 1;
        if (rem >= 2) cp_wait<2>();
        else if (rem == 1) cp_wait<1>();
        else cp_wait<0>();
        __syncthreads();

        if (kt + XST - 1 < nkt) issue(kt + XST - 1, (kt + XST - 1) % XST);

        int st = kt % XST;
        const __half* cAh = sAh + st * XBM * XAP;
        const __half* cWh = sWh + st * XBN * XAP;
        const __half* cWl = sWl + st * XBN * XAP;

#pragma unroll
        for (int kc = 0; kc < XBK; kc += 16) {
            unsigned ah[2][4], bh[8][2], bl[8][2];
#pragma unroll
            for (int mi = 0; mi < 2; mi++) {
                int r = wm * 32 + mi * 16 + gq;
                ah[mi][0] = *(unsigned*)&cAh[r * XAP + kc + 2 * tg];
                ah[mi][1] = *(unsigned*)&cAh[(r + 8) * XAP + kc + 2 * tg];
                ah[mi][2] = *(unsigned*)&cAh[r * XAP + kc + 2 * tg + 8];
                ah[mi][3] = *(unsigned*)&cAh[(r + 8) * XAP + kc + 2 * tg + 8];
            }
#pragma unroll
            for (int ni = 0; ni < 8; ni++) {
                int n = wn * 64 + ni * 8 + gq;
                bh[ni][0] = *(unsigned*)&cWh[n * XAP + kc + 2 * tg];
                bh[ni][1] = *(unsigned*)&cWh[n * XAP + kc + 2 * tg + 8];
                bl[ni][0] = *(unsigned*)&cWl[n * XAP + kc + 2 * tg];
                bl[ni][1] = *(unsigned*)&cWl[n * XAP + kc + 2 * tg + 8];
            }
#pragma unroll
            for (int mi = 0; mi < 2; mi++)
#pragma unroll
                for (int ni = 0; ni < 8; ni++) {
                    mma16816(acc[mi][ni], ah[mi], bh[ni]);
                    mma16816(acc[mi][ni], ah[mi], bl[ni]);
                }
        }
    }

#pragma unroll
    for (int mi = 0; mi < 2; mi++)
#pragma unroll
        for (int ni = 0; ni < 8; ni++) {
            int row = m0 + wm * 32 + mi * 16 + gq;
            int col = n0 + wn * 64 + ni * 8 + 2 * tg;
            float b0v = bias[col], b1v = bias[col + 1];
            g_xw[(size_t)row * G4 + col]           = acc[mi][ni][0] + b0v;
            g_xw[(size_t)row * G4 + col + 1]       = acc[mi][ni][1] + b1v;
            g_xw[(size_t)(row + 8) * G4 + col]     = acc[mi][ni][2] + b0v;
            g_xw[(size_t)(row + 8) * G4 + col + 1] = acc[mi][ni][3] + b1v;
        }
}

// ---------------- persistent recurrent kernel: split-K, fp16 2-pass ----------------
// 128 CTAs x 512 threads. Half h computes 64x64 tile over K[h*256, h*256+256),
// 4 k-tiles each, h_hi only, double buffer, order: wait -> bar -> issue -> consume.
// SMEM: sWh 64x528 (67584) | sWl (67584) | half0 2x10240 | half1 2x10240 | red 17408
#define SMEM_REC 193536
#define SWP 528
#define STP 80
#define RKT 64
#define HB_OFF 135168
#define RED_OFF 176128
#define REDP 68

__global__ __launch_bounds__(512, 1) void k_rec(int layer) {
    extern __shared__ char sm[];
    __half (*sWh)[SWP] = (__half(*)[SWP])(sm);
    __half (*sWl)[SWP] = (__half(*)[SWP])(sm + 67584);
    float* red = (float*)(sm + RED_OFF);

    const __half *Whg, *Wlg;
    __half *HOhi, *HOlo;
    if (layer == 0)      { Whg = g_whh1_hi; Wlg = g_whh1_lo; HOhi = g_h1_hi; HOlo = g_h1_lo; }
    else if (layer == 1) { Whg = g_whh2_hi; Wlg = g_whh2_lo; HOhi = g_h2_hi; HOlo = g_h2_lo; }
    else                 { Whg = g_whh3_hi; Wlg = g_whh3_lo; HOhi = g_h3_hi; HOlo = g_h3_lo; }

    int tid = threadIdx.x;
    int half = tid >> 8;
    int htid = tid & 255;
    int lane = tid & 31;
    int hw = htid >> 5;
    int bx = blockIdx.x;
    int bhid = bx >> 2;
    int bbat = bx & 3;
    int m0 = bbat * 64;
    int n0 = bhid * 16;
    int wm = hw >> 1, wn = hw & 1;
    int gq = lane >> 2, tg = lane & 3;
    int koff = half * 256;

    // resident W slice (hi+lo)
    for (int idx = tid; idx < 64 * 256; idx += 512) {
        int r = idx >> 8;
        int c = (idx & 255) * 2;
        int grow = (r >> 4) * HH + n0 + (r & 15);
        size_t gi = (size_t)grow * HH + c;
        *(unsigned*)&sWh[r][c] = *(const unsigned*)&Whg[gi];
        *(unsigned*)&sWl[r][c] = *(const unsigned*)&Wlg[gi];
    }
    __syncthreads();

    unsigned hb = smem_u32(sm) + HB_OFF + (unsigned)half * 20480u;
    int lrow = htid >> 2;             // 64 rows, 4 threads/row
    int lcol = (htid & 3) * 16;

    int row0 = wm * 16 + gq;
    int jloc = wn * 8 + 2 * tg;
    int jst  = 4 * tg + 2 * wn;

    unsigned base_t = (unsigned)layer * SS;

    float cb[2][2] = {{0.f, 0.f}, {0.f, 0.f}};
    float xwn[4][2][2];
    if (half == 0) {
        const float* xwb = g_xw + ((size_t)0 * BB + m0 + row0) * G4;
#pragma unroll
        for (int g = 0; g < 4; g++)
#pragma unroll
            for (int rr = 0; rr < 2; rr++) {
                float2 v = *(const float2*)(xwb + (size_t)rr * 8 * G4 + g * HH + n0 + jloc);
                xwn[g][rr][0] = v.x; xwn[g][rr][1] = v.y;
            }
    }

    for (int s = 0; s < SS; s++) {
        float acc[4][4];
#pragma unroll
        for (int g = 0; g < 4; g++)
#pragma unroll
            for (int r = 0; r < 4; r++) acc[g][r] = 0.f;

        if (s > 0) {
            const __half* Hh = HOhi + ((size_t)(s - 1) * BB + m0) * HH;

            auto issueH = [&](int kt) {
                int b = kt & 1;
                const __half* gh = Hh + (size_t)lrow * HH + koff + kt * RKT + lcol;
                unsigned d = (unsigned)(b * 10240 + (lrow * STP + lcol) * 2);
                cp16(hb + d, gh);  cp16(hb + d + 16, gh + 8);
                cp_commit();
            };

            issueH(0);
#pragma unroll
            for (int kt = 0; kt < 4; kt++) {
                cp_wait<0>();                     // tile kt landed (this thread's copies)
                bar_half(half);                   // all threads' copies visible; prev buffer free
                if (kt + 1 < 4) issueH(kt + 1);

                int b = kt & 1;
                const __half* cHh = (const __half*)(sm + HB_OFF + half * 20480 + b * 10240);
#pragma unroll
                for (int kc = 0; kc < RKT; kc += 16) {
                    int kw = koff + kt * RKT + kc;
                    unsigned ah[4], bh[4][2], bl[4][2];
                    uint2 t;
                    t = *(uint2*)&cHh[row0 * STP + kc + 4 * tg];        ah[0] = t.x; ah[2] = t.y;
                    t = *(uint2*)&cHh[(row0 + 8) * STP + kc + 4 * tg];  ah[1] = t.x; ah[3] = t.y;
#pragma unroll
                    for (int g = 0; g < 4; g++) {
                        int n = g * 16 + wn * 8 + gq;
                        t = *(uint2*)&sWh[n][kw + 4 * tg];  bh[g][0] = t.x; bh[g][1] = t.y;
                        t = *(uint2*)&sWl[n][kw + 4 * tg];  bl[g][0] = t.x; bl[g][1] = t.y;
                    }
#pragma unroll
                    for (int g = 0; g < 4; g++) {
                        mma16816(acc[g], ah, bh[g]);
                        mma16816(acc[g], ah, bl[g]);
                    }
                }
            }
        }

        // ---- cross-half reduction ----
        __syncthreads();
        if (s > 0) {
            if (half == 1) {
#pragma unroll
                for (int g = 0; g < 4; g++)
#pragma unroll
                    for (int rr = 0; rr < 2; rr++)
#pragma unroll
                        for (int cc = 0; cc < 2; cc++)
                            red[(row0 + rr * 8) * REDP + g * 16 + jloc + cc] = acc[g][rr * 2 + cc];
            }
            __syncthreads();
            if (half == 0) {
#pragma unroll
                for (int g = 0; g < 4; g++)
#pragma unroll
                    for (int rr = 0; rr < 2; rr++)
#pragma unroll
                        for (int cc = 0; cc < 2; cc++)
                            acc[g][rr * 2 + cc] += red[(row0 + rr * 8) * REDP + g * 16 + jloc + cc];
            }
        }

        if (half == 0) {
            float xwf[4][2][2];
#pragma unroll
            for (int g = 0; g < 4; g++)
#pragma unroll
                for (int rr = 0; rr < 2; rr++) {
                    xwf[g][rr][0] = xwn[g][rr][0];
                    xwf[g][rr][1] = xwn[g][rr][1];
                }
            if (s + 1 < SS) {
                const float* xwb = g_xw + ((size_t)(s + 1) * BB + m0 + row0) * G4;
#pragma unroll
                for (int g = 0; g < 4; g++)
#pragma unroll
                    for (int rr = 0; rr < 2; rr++) {
                        float2 v = *(const float2*)(xwb + (size_t)rr * 8 * G4 + g * HH + n0 + jloc);
                        xwn[g][rr][0] = v.x; xwn[g][rr][1] = v.y;
                    }
            }

#pragma unroll
            for (int rr = 0; rr < 2; rr++) {
                __half hh[2], hl[2];
#pragma unroll
                for (int cc = 0; cc < 2; cc++) {
                    int fi = rr * 2 + cc;
                    float pi = acc[0][fi] + xwf[0][rr][cc];
                    float pf = acc[1][fi] + xwf[1][rr][cc];
                    float pg = acc[2][fi] + xwf[2][rr][cc];
                    float po = acc[3][fi] + xwf[3][rr][cc];
                    float iv = fsigmoid(pi);
                    float fv = fsigmoid(pf);
                    float gv = felu(pg);
                    float ov = fsigmoid(po);
                    float cn = fv * cb[rr][cc] + iv * gv;
                    float hv = ov * felu(cn);
                    cb[rr][cc] = cn;
                    split_f16(hv, hh[cc], hl[cc]);
                }
                size_t hidx = ((size_t)s * BB + m0 + row0 + rr * 8) * HH + n0 + jst;
                *(unsigned*)(HOhi + hidx) = *(unsigned*)hh;
                if (layer == 2)                     // lo consumed only by k_fc
                    *(unsigned*)(HOlo + hidx) = *(unsigned*)hl;
            }
        }

        gbar_g(base_t + (unsigned)s + 1u, bbat);
    }
}

// ---------------- final FC: out[b] = h3[S-1,b,:] . fc_w + fc_b (hi+lo, permuted) ----
__global__ void k_fc(const float* __restrict__ fcw, const float* __restrict__ fcb,
                     float* __restrict__ out) {
    __shared__ float red[4];
    int b = blockIdx.x, tid = threadIdx.x;
    size_t base = ((size_t)(SS - 1) * BB + b) * HH;
    float sum = 0.f;
    for (int p = tid; p < HH; p += 128) {
        int l = (p & ~15) | l16(p & 15);
        sum += (__half2float(g_h3_hi[base + p]) + __half2float(g_h3_lo[base + p])) * fcw[l];
    }
#pragma unroll
    for (int o = 16; o; o >>= 1) sum += __shfl_xor_sync(0xFFFFFFFFu, sum, o);
    if ((tid & 31) == 0) red[tid >> 5] = sum;
    __syncthreads();
    if (tid == 0) out[b] = red[0] + red[1] + red[2] + red[3] + fcb[0];
}

// ---------------- launch ----------------
extern "C" void kernel_launch(void* const* d_in, const int* in_sizes, int n_in,
                              void* d_out, int out_size) {
    const float* x    = (const float*)d_in[0];
    const float* wih1 = (const float*)d_in[1];
    const float* whh1 = (const float*)d_in[2];
    const float* b1   = (const float*)d_in[3];
    const float* wih2 = (const float*)d_in[4];
    const float* whh2 = (const float*)d_in[5];
    const float* b2   = (const float*)d_in[6];
    const float* wih3 = (const float*)d_in[7];
    const float* whh3 = (const float*)d_in[8];
    const float* b3   = (const float*)d_in[9];
    const float* fcw  = (const float*)d_in[10];
    const float* fcb  = (const float*)d_in[11];

    cudaFuncSetAttribute(k_rec, cudaFuncAttributeMaxDynamicSharedMemorySize, SMEM_REC);
    cudaFuncSetAttribute(k_gemm_x1, cudaFuncAttributeMaxDynamicSharedMemorySize, X1_SMEM);
    cudaFuncSetAttribute(k_gemm_h, cudaFuncAttributeMaxDynamicSharedMemorySize, XH_SMEM);

    // 0 split, 1 barinit, 2 gemm_x1, 3 rec0, 4 gemm_h, 5 rec1 (ncu -s 5), 6 gemm_h, 7 rec2, 8 fc
    size_t nsp = NSPLIT;
    k_split_all<<<(unsigned)((nsp + 255) / 256), 256>>>(x, wih1, whh1, wih2, whh2, wih3, whh3);
    k_bar_init<<<1, 128>>>();

    dim3 gg(G4 / XBN, (SS * BB) / XBM);
    k_gemm_x1<<<gg, 256, X1_SMEM>>>(b1);
    k_rec<<<NCTA, 512, SMEM_REC>>>(0);
    k_gemm_h<<<gg, 256, XH_SMEM>>>(1, b2);
    k_rec<<<NCTA, 512, SMEM_REC>>>(1);
    k_gemm_h<<<gg, 256, XH_SMEM>>>(2, b3);
    k_rec<<<NCTA, 512, SMEM_REC>>>(2);
    k_fc<<<BB, 128>>>(fcw, fcb, (float*)d_out);
}